// round 15
// baseline (speedup 1.0000x reference)
#include <cuda_runtime.h>
#include <cuda_fp16.h>
#include <mma.h>

using namespace nvcuda;

#define N_NODES 50000
#define N_EDGES 800000
#define D 64
#define D4 (D / 4)
#define NCLS 16
#define ROW_TILES ((N_NODES + 63) / 64)     // 782
#define GATHER_NODES_PER_BLOCK 16

// ---------------- scratch ----------------
__device__ float2 g_dc[N_NODES];      // .x = weighted deg (init 1 = self loop), .y = count
__device__ float  g_dinv[N_NODES];
__device__ int    g_count[N_NODES];
__device__ int    g_off[N_NODES];
__device__ int    g_cursor[N_NODES];
__device__ int    g_total;
__device__ int2   g_edge[N_EDGES];    // CSR slot: {src, w bits} — ONE 8B store per edge
__device__ uint2  g_h2[N_NODES * 16]; // h' = dinv*h in fp16: 64 halves per row
__device__ float4 g_agg4[N_NODES * D4];

// ---------------- prep: deg=1 (self loop), count=0, total=0 ----------------
__global__ void prep_kernel(float2* dc, int* total) {
    int i = blockIdx.x * blockDim.x + threadIdx.x;
    if (i < N_NODES) dc[i] = make_float2(1.0f, 0.0f);
    if (i == 0) *total = 0;
}

// ---------------- weighted degree + count: one v2 vector RED per edge ----------------
__global__ void deg_count_kernel(const int* __restrict__ ei,
                                 const float* __restrict__ ew,
                                 float2* dc) {
    int e = blockIdx.x * blockDim.x + threadIdx.x;
    if (e < N_EDGES) {
        int c = ei[N_EDGES + e];
        float w = ew[e];
        asm volatile("red.global.add.v2.f32 [%0], {%1, %2};"
                     :: "l"(dc + c), "f"(w), "f"(1.0f) : "memory");
    }
}

// ---------------- alloc: dinv + warp-aggregated CSR slot allocation (order-free) ----------------
__global__ void alloc_kernel(const float2* __restrict__ dc,
                             int* __restrict__ count,
                             float* __restrict__ dinv,
                             int* __restrict__ off,
                             int* __restrict__ cursor,
                             int* __restrict__ total) {
    const int i = blockIdx.x * blockDim.x + threadIdx.x;
    const int lane = threadIdx.x & 31;

    int c = 0;
    if (i < N_NODES) {
        float2 v = dc[i];
        c = (int)v.y;                 // count is integral, exact in fp32
        dinv[i] = rsqrtf(v.x);        // deg >= 1 (self loop)
        count[i] = c;
    }

    int incl = c;
    #pragma unroll
    for (int d = 1; d < 32; d <<= 1) {
        int v = __shfl_up_sync(0xFFFFFFFFu, incl, d);
        if (lane >= d) incl += v;
    }
    const int warpsum = __shfl_sync(0xFFFFFFFFu, incl, 31);

    int base = 0;
    if (lane == 31) base = atomicAdd(total, warpsum);
    base = __shfl_sync(0xFFFFFFFFu, base, 31);

    const int o = base + incl - c;   // exclusive offset
    if (i < N_NODES) { off[i] = o; cursor[i] = o; }
}

// ---------------- CSR fill: one packed 8B (src, w) store per slot ----------------
__global__ void fill_kernel(const int* __restrict__ ei,
                            const float* __restrict__ ew,
                            int* __restrict__ cursor,
                            int2* __restrict__ edge) {
    int e = blockIdx.x * blockDim.x + threadIdx.x;
    if (e < N_EDGES) {
        int r = ei[e];
        int c = ei[N_EDGES + e];
        float w = ew[e];
        int slot = atomicAdd(&cursor[c], 1);
        edge[slot] = make_int2(r, __float_as_int(w));
    }
}

// ---------------- tensor-core 64x64 GEMM: h'fp16 = dinv * ((relu?)(X) @ W) ----------------
template <bool RELU_IN>
__global__ void gemm64_wmma_kernel(const float* __restrict__ X,
                                   const float* __restrict__ W,
                                   const float* __restrict__ dinv,
                                   __half* __restrict__ H) {
    __shared__ __half Xh[64][72];               // 72-pad: 144B rows
    __shared__ __half Wh[64][72];
    __shared__ float  scratch[8][16][20];

    const int tid = threadIdx.x;
    const int warp = tid >> 5;
    const int lane = tid & 31;
    const int rb = blockIdx.x * 64;
    const int rows = min(64, N_NODES - rb);

    for (int i = tid; i < 64 * 64; i += 256)
        Wh[i >> 6][i & 63] = __float2half(W[i]);
    for (int i = tid; i < rows * 64; i += 256) {
        float v = X[rb * 64 + i];
        if (RELU_IN) v = fmaxf(v, 0.0f);
        Xh[i >> 6][i & 63] = __float2half(v);
    }
    if (rows < 64) {
        for (int i = rows * 64 + tid; i < 64 * 64; i += 256)
            Xh[i >> 6][i & 63] = __half(0.0f);
    }
    __syncthreads();

    wmma::fragment<wmma::matrix_a, 16, 16, 16, __half, wmma::row_major> a;
    wmma::fragment<wmma::matrix_b, 16, 16, 16, __half, wmma::row_major> bf;
    wmma::fragment<wmma::accumulator, 16, 16, 16, float> c;

    #pragma unroll
    for (int i = 0; i < 2; i++) {
        const int t  = warp * 2 + i;
        const int tr = t >> 2;
        const int tc = t & 3;
        wmma::fill_fragment(c, 0.0f);
        #pragma unroll
        for (int kk = 0; kk < 4; kk++) {
            wmma::load_matrix_sync(a, &Xh[tr * 16][kk * 16], 72);
            wmma::load_matrix_sync(bf, &Wh[kk * 16][tc * 16], 72);
            wmma::mma_sync(c, a, bf, c);
        }
        wmma::store_matrix_sync(&scratch[warp][0][0], c, 20, wmma::mem_row_major);
        __syncwarp();
        #pragma unroll
        for (int j = lane; j < 128; j += 32) {
            const int r  = j >> 3;
            const int cc = (j & 7) * 2;
            const int gr = rb + tr * 16 + r;
            if (gr < N_NODES) {
                const float dv = dinv[gr];
                __half2 hv = __floats2half2_rn(dv * scratch[warp][r][cc],
                                               dv * scratch[warp][r][cc + 1]);
                *reinterpret_cast<__half2*>(&H[gr * 64 + tc * 16 + cc]) = hv;
            }
        }
        __syncwarp();
    }
}

// ---------------- CSR gather: agg[n] = dinv[n]*(sum w*h'[src] + h'[n]) + b ----------------
// block (16,16): x = lane (4 halves = 8B each), y = node within block.
__global__ void gather_kernel(const int* __restrict__ off,
                              const int* __restrict__ count,
                              const int2* __restrict__ edge,
                              const float* __restrict__ dinv,
                              const float* __restrict__ b,
                              const uint2* __restrict__ h2,
                              float4* __restrict__ agg4) {
    const int sub = threadIdx.x;
    const int n = blockIdx.x * GATHER_NODES_PER_BLOCK + threadIdx.y;
    if (n >= N_NODES) return;

    const int beg = off[n];
    const int end = beg + count[n];

    float4 acc0 = make_float4(0.f, 0.f, 0.f, 0.f);
    float4 acc1 = make_float4(0.f, 0.f, 0.f, 0.f);
    int s = beg;
    for (; s + 1 < end; s += 2) {
        const int2 e0 = edge[s];
        const int2 e1 = edge[s + 1];
        const float w0 = __int_as_float(e0.y);
        const float w1 = __int_as_float(e1.y);
        const uint2 hv0 = h2[e0.x * 16 + sub];
        const uint2 hv1 = h2[e1.x * 16 + sub];
        const float2 a0 = __half22float2(*reinterpret_cast<const __half2*>(&hv0.x));
        const float2 a1 = __half22float2(*reinterpret_cast<const __half2*>(&hv0.y));
        const float2 c0 = __half22float2(*reinterpret_cast<const __half2*>(&hv1.x));
        const float2 c1 = __half22float2(*reinterpret_cast<const __half2*>(&hv1.y));
        acc0.x = fmaf(w0, a0.x, acc0.x);
        acc0.y = fmaf(w0, a0.y, acc0.y);
        acc0.z = fmaf(w0, a1.x, acc0.z);
        acc0.w = fmaf(w0, a1.y, acc0.w);
        acc1.x = fmaf(w1, c0.x, acc1.x);
        acc1.y = fmaf(w1, c0.y, acc1.y);
        acc1.z = fmaf(w1, c1.x, acc1.z);
        acc1.w = fmaf(w1, c1.y, acc1.w);
    }
    if (s < end) {
        const int2 e0 = edge[s];
        const float w = __int_as_float(e0.y);
        const uint2 hv = h2[e0.x * 16 + sub];
        const float2 a0 = __half22float2(*reinterpret_cast<const __half2*>(&hv.x));
        const float2 a1 = __half22float2(*reinterpret_cast<const __half2*>(&hv.y));
        acc0.x = fmaf(w, a0.x, acc0.x);
        acc0.y = fmaf(w, a0.y, acc0.y);
        acc0.z = fmaf(w, a1.x, acc0.z);
        acc0.w = fmaf(w, a1.y, acc0.w);
    }

    const float di = dinv[n];
    const uint2 hn = h2[n * 16 + sub];
    const float2 s0 = __half22float2(*reinterpret_cast<const __half2*>(&hn.x));
    const float2 s1 = __half22float2(*reinterpret_cast<const __half2*>(&hn.y));
    const float4 bv = reinterpret_cast<const float4*>(b)[sub];
    agg4[n * D4 + sub] = make_float4(fmaf(di, acc0.x + acc1.x + s0.x, bv.x),
                                     fmaf(di, acc0.y + acc1.y + s0.y, bv.y),
                                     fmaf(di, acc0.z + acc1.z + s1.x, bv.z),
                                     fmaf(di, acc0.w + acc1.w + s1.y, bv.w));
}

// ---------------- fused MLP head: wmma stage1 + SIMT stage2 + sigmoid ----------------
__global__ void mlp_kernel(const float* __restrict__ A,
                           const float* __restrict__ Wm1,
                           const float* __restrict__ bm1,
                           const float* __restrict__ Wm2,
                           const float* __restrict__ bm2,
                           float* __restrict__ out) {
    __shared__ __half Xh[64][72];
    __shared__ __half W1h[64][72];
    __shared__ float  T[64][68];
    __shared__ float  W2s[64][NCLS];
    __shared__ float  b1s[64];
    __shared__ float  b2s[NCLS];

    const int tid = threadIdx.x;
    const int warp = tid >> 5;
    const int rb = blockIdx.x * 64;
    const int rows = min(64, N_NODES - rb);

    for (int i = tid; i < 64 * 64; i += 256)
        W1h[i >> 6][i & 63] = __float2half(Wm1[i]);
    for (int i = tid; i < 64 * NCLS; i += 256)
        W2s[i / NCLS][i % NCLS] = Wm2[i];
    if (tid < 64) b1s[tid] = bm1[tid];
    if (tid < NCLS) b2s[tid] = bm2[tid];
    for (int i = tid; i < rows * 64; i += 256)
        Xh[i >> 6][i & 63] = __float2half(fmaxf(A[rb * 64 + i], 0.0f));
    if (rows < 64) {
        for (int i = rows * 64 + tid; i < 64 * 64; i += 256)
            Xh[i >> 6][i & 63] = __half(0.0f);
    }
    __syncthreads();

    // stage 1: T = relu(relu(A) @ Wm1 + bm1) via wmma (16 tiles, 2 per warp)
    {
        wmma::fragment<wmma::matrix_a, 16, 16, 16, __half, wmma::row_major> a;
        wmma::fragment<wmma::matrix_b, 16, 16, 16, __half, wmma::row_major> bf;
        wmma::fragment<wmma::accumulator, 16, 16, 16, float> c;
        #pragma unroll
        for (int i = 0; i < 2; i++) {
            const int t  = warp * 2 + i;
            const int tr = t >> 2;
            const int tc = t & 3;
            wmma::fill_fragment(c, 0.0f);
            #pragma unroll
            for (int kk = 0; kk < 4; kk++) {
                wmma::load_matrix_sync(a, &Xh[tr * 16][kk * 16], 72);
                wmma::load_matrix_sync(bf, &W1h[kk * 16][tc * 16], 72);
                wmma::mma_sync(c, a, bf, c);
            }
            wmma::store_matrix_sync(&T[tr * 16][tc * 16], c, 68, wmma::mem_row_major);
        }
    }
    __syncthreads();

    // bias + relu sweep
    for (int i = tid; i < 64 * 64; i += 256) {
        const int r = i >> 6, cc = i & 63;
        T[r][cc] = fmaxf(T[r][cc] + b1s[cc], 0.0f);
    }
    __syncthreads();

    // stage 2: out = sigmoid(T @ Wm2 + bm2); 256 threads = 16 rows x 16 cls
    const int row16 = tid >> 4;
    const int cls   = tid & 15;
    #pragma unroll
    for (int rr = 0; rr < 4; rr++) {
        const int row = rr * 16 + row16;
        const int gr = rb + row;
        float acc2 = b2s[cls];
        #pragma unroll
        for (int k = 0; k < 64; k++)
            acc2 = fmaf(T[row][k], W2s[k][cls], acc2);
        if (gr < N_NODES)
            out[gr * NCLS + cls] = 1.0f / (1.0f + __expf(-acc2));
    }
}

// ---------------- launch ----------------
extern "C" void kernel_launch(void* const* d_in, const int* in_sizes, int n_in,
                              void* d_out, int out_size) {
    const float* x    = (const float*)d_in[0];
    const int*   ei   = (const int*)d_in[1];
    const float* ew   = (const float*)d_in[2];
    const float* W1   = (const float*)d_in[3];
    const float* b1   = (const float*)d_in[4];
    const float* W2   = (const float*)d_in[5];
    const float* b2   = (const float*)d_in[6];
    const float* Wm1  = (const float*)d_in[7];
    const float* bm1  = (const float*)d_in[8];
    const float* Wm2  = (const float*)d_in[9];
    const float* bm2  = (const float*)d_in[10];
    float* out = (float*)d_out;

    float2 *p_dc;
    float *p_dinv;
    int *p_count, *p_off, *p_cursor, *p_total;
    int2 *p_edge;
    uint2 *p_h2;
    float4 *p_agg4;
    cudaGetSymbolAddress((void**)&p_dc,     g_dc);
    cudaGetSymbolAddress((void**)&p_dinv,   g_dinv);
    cudaGetSymbolAddress((void**)&p_count,  g_count);
    cudaGetSymbolAddress((void**)&p_off,    g_off);
    cudaGetSymbolAddress((void**)&p_cursor, g_cursor);
    cudaGetSymbolAddress((void**)&p_total,  g_total);
    cudaGetSymbolAddress((void**)&p_edge,   g_edge);
    cudaGetSymbolAddress((void**)&p_h2,     g_h2);
    cudaGetSymbolAddress((void**)&p_agg4,   g_agg4);
    __half* p_h   = (__half*)p_h2;
    float*  p_agg = (float*)p_agg4;

    const dim3 blkg(16, GATHER_NODES_PER_BLOCK);
    const int GATHER_GRID = (N_NODES + GATHER_NODES_PER_BLOCK - 1) / GATHER_NODES_PER_BLOCK;

    // CSR build (reused by both layers)
    prep_kernel<<<(N_NODES + 255) / 256, 256>>>(p_dc, p_total);
    deg_count_kernel<<<(N_EDGES + 255) / 256, 256>>>(ei, ew, p_dc);
    alloc_kernel<<<(N_NODES + 255) / 256, 256>>>(p_dc, p_count, p_dinv, p_off, p_cursor, p_total);
    fill_kernel<<<(N_EDGES + 255) / 256, 256>>>(ei, ew, p_cursor, p_edge);

    // layer 1
    gemm64_wmma_kernel<false><<<ROW_TILES, 256>>>(x, W1, p_dinv, p_h);
    gather_kernel<<<GATHER_GRID, blkg>>>(p_off, p_count, p_edge, p_dinv, b1, p_h2, p_agg4);

    // layer 2
    gemm64_wmma_kernel<true><<<ROW_TILES, 256>>>(p_agg, W2, p_dinv, p_h);
    gather_kernel<<<GATHER_GRID, blkg>>>(p_off, p_count, p_edge, p_dinv, b2, p_h2, p_agg4);

    // MLP head + sigmoid
    mlp_kernel<<<ROW_TILES, 256>>>(p_agg, Wm1, bm1, Wm2, bm2, out);
}

// round 16
// speedup vs baseline: 1.0165x; 1.0165x over previous
#include <cuda_runtime.h>
#include <cuda_fp16.h>
#include <mma.h>

using namespace nvcuda;

#define N_NODES 50000
#define N_EDGES 800000
#define D 64
#define NCLS 16
#define ROW_TILES ((N_NODES + 63) / 64)     // 782
#define GATHER_NODES_PER_BLOCK 16

// ---------------- scratch (zero-initialized at module load) ----------------
__device__ float2 g_dc[N_NODES];      // .x = sum of edge w into node, .y = count (RESTORED to 0 by alloc)
__device__ float  g_dinv[N_NODES];
__device__ int    g_count[N_NODES];
__device__ int    g_off[N_NODES];
__device__ int    g_cursor[N_NODES];
__device__ int    g_total;            // restored to 0 by gather (layer-1 instance)
__device__ int2   g_edge[N_EDGES];    // CSR slot: {src, w bits}
__device__ uint2  g_h2[N_NODES * 16]; // h' = dinv*h in fp16: 64 halves per row
__device__ uint2  g_agg2[N_NODES * 16]; // agg in fp16: 64 halves per row

// helpers
__device__ __forceinline__ float ldf(const float* p, int i)  { return p[i]; }
__device__ __forceinline__ float ldf(const __half* p, int i) { return __half2float(p[i]); }

// ---------------- weighted degree + count: one v2 vector RED per edge ----------------
__global__ void deg_count_kernel(const int* __restrict__ ei,
                                 const float* __restrict__ ew,
                                 float2* dc) {
    int e = blockIdx.x * blockDim.x + threadIdx.x;
    if (e < N_EDGES) {
        int c = ei[N_EDGES + e];
        float w = ew[e];
        asm volatile("red.global.add.v2.f32 [%0], {%1, %2};"
                     :: "l"(dc + c), "f"(w), "f"(1.0f) : "memory");
    }
}

// ---------------- alloc: dinv + warp-aggregated slot allocation; restores dc=0 ----------------
__global__ void alloc_kernel(float2* __restrict__ dc,
                             int* __restrict__ count,
                             float* __restrict__ dinv,
                             int* __restrict__ off,
                             int* __restrict__ cursor,
                             int* __restrict__ total) {
    const int i = blockIdx.x * blockDim.x + threadIdx.x;
    const int lane = threadIdx.x & 31;

    int c = 0;
    if (i < N_NODES) {
        float2 v = dc[i];
        dc[i] = make_float2(0.0f, 0.0f);   // restore invariant for next launch
        c = (int)v.y;                      // count is integral, exact in fp32
        dinv[i] = rsqrtf(1.0f + v.x);      // self-loop weight 1 added here
        count[i] = c;
    }

    int incl = c;
    #pragma unroll
    for (int d = 1; d < 32; d <<= 1) {
        int v = __shfl_up_sync(0xFFFFFFFFu, incl, d);
        if (lane >= d) incl += v;
    }
    const int warpsum = __shfl_sync(0xFFFFFFFFu, incl, 31);

    int base = 0;
    if (lane == 31) base = atomicAdd(total, warpsum);
    base = __shfl_sync(0xFFFFFFFFu, base, 31);

    const int o = base + incl - c;   // exclusive offset
    if (i < N_NODES) { off[i] = o; cursor[i] = o; }
}

// ---------------- CSR fill: one packed 8B (src, w) store per slot ----------------
__global__ void fill_kernel(const int* __restrict__ ei,
                            const float* __restrict__ ew,
                            int* __restrict__ cursor,
                            int2* __restrict__ edge) {
    int e = blockIdx.x * blockDim.x + threadIdx.x;
    if (e < N_EDGES) {
        int r = ei[e];
        int c = ei[N_EDGES + e];
        float w = ew[e];
        int slot = atomicAdd(&cursor[c], 1);
        edge[slot] = make_int2(r, __float_as_int(w));
    }
}

// ---------------- tensor-core 64x64 GEMM: h'fp16 = dinv * ((relu?)(X) @ W) ----------------
template <bool RELU_IN, typename TIN>
__global__ void gemm64_wmma_kernel(const TIN* __restrict__ X,
                                   const float* __restrict__ W,
                                   const float* __restrict__ dinv,
                                   __half* __restrict__ H) {
    __shared__ __half Xh[64][72];               // 72-pad: 144B rows
    __shared__ __half Wh[64][72];
    __shared__ float  scratch[8][16][20];

    const int tid = threadIdx.x;
    const int warp = tid >> 5;
    const int lane = tid & 31;
    const int rb = blockIdx.x * 64;
    const int rows = min(64, N_NODES - rb);

    for (int i = tid; i < 64 * 64; i += 256)
        Wh[i >> 6][i & 63] = __float2half(W[i]);
    for (int i = tid; i < rows * 64; i += 256) {
        float v = ldf(X, rb * 64 + i);
        if (RELU_IN) v = fmaxf(v, 0.0f);
        Xh[i >> 6][i & 63] = __float2half(v);
    }
    if (rows < 64) {
        for (int i = rows * 64 + tid; i < 64 * 64; i += 256)
            Xh[i >> 6][i & 63] = __half(0.0f);
    }
    __syncthreads();

    wmma::fragment<wmma::matrix_a, 16, 16, 16, __half, wmma::row_major> a;
    wmma::fragment<wmma::matrix_b, 16, 16, 16, __half, wmma::row_major> bf;
    wmma::fragment<wmma::accumulator, 16, 16, 16, float> c;

    #pragma unroll
    for (int i = 0; i < 2; i++) {
        const int t  = warp * 2 + i;
        const int tr = t >> 2;
        const int tc = t & 3;
        wmma::fill_fragment(c, 0.0f);
        #pragma unroll
        for (int kk = 0; kk < 4; kk++) {
            wmma::load_matrix_sync(a, &Xh[tr * 16][kk * 16], 72);
            wmma::load_matrix_sync(bf, &Wh[kk * 16][tc * 16], 72);
            wmma::mma_sync(c, a, bf, c);
        }
        wmma::store_matrix_sync(&scratch[warp][0][0], c, 20, wmma::mem_row_major);
        __syncwarp();
        #pragma unroll
        for (int j = lane; j < 128; j += 32) {
            const int r  = j >> 3;
            const int cc = (j & 7) * 2;
            const int gr = rb + tr * 16 + r;
            if (gr < N_NODES) {
                const float dv = dinv[gr];
                __half2 hv = __floats2half2_rn(dv * scratch[warp][r][cc],
                                               dv * scratch[warp][r][cc + 1]);
                *reinterpret_cast<__half2*>(&H[gr * 64 + tc * 16 + cc]) = hv;
            }
        }
        __syncwarp();
    }
}

// ---------------- CSR gather: agg[n] = fp16( dinv[n]*(sum w*h'[src] + h'[n]) + b ) ----------------
// block (16,16): x = lane (4 halves = 8B each), y = node within block.
template <bool ZERO_TOTAL>
__global__ void gather_kernel(const int* __restrict__ off,
                              const int* __restrict__ count,
                              const int2* __restrict__ edge,
                              const float* __restrict__ dinv,
                              const float* __restrict__ b,
                              const uint2* __restrict__ h2,
                              uint2* __restrict__ agg2,
                              int* __restrict__ total) {
    if (ZERO_TOTAL && blockIdx.x == 0 && threadIdx.x == 0 && threadIdx.y == 0)
        *total = 0;                        // restore invariant for next launch

    const int sub = threadIdx.x;
    const int n = blockIdx.x * GATHER_NODES_PER_BLOCK + threadIdx.y;
    if (n >= N_NODES) return;

    const int beg = off[n];
    const int end = beg + count[n];

    float4 acc0 = make_float4(0.f, 0.f, 0.f, 0.f);
    float4 acc1 = make_float4(0.f, 0.f, 0.f, 0.f);
    int s = beg;
    for (; s + 1 < end; s += 2) {
        const int2 e0 = edge[s];
        const int2 e1 = edge[s + 1];
        const float w0 = __int_as_float(e0.y);
        const float w1 = __int_as_float(e1.y);
        const uint2 hv0 = h2[e0.x * 16 + sub];
        const uint2 hv1 = h2[e1.x * 16 + sub];
        const float2 a0 = __half22float2(*reinterpret_cast<const __half2*>(&hv0.x));
        const float2 a1 = __half22float2(*reinterpret_cast<const __half2*>(&hv0.y));
        const float2 c0 = __half22float2(*reinterpret_cast<const __half2*>(&hv1.x));
        const float2 c1 = __half22float2(*reinterpret_cast<const __half2*>(&hv1.y));
        acc0.x = fmaf(w0, a0.x, acc0.x);
        acc0.y = fmaf(w0, a0.y, acc0.y);
        acc0.z = fmaf(w0, a1.x, acc0.z);
        acc0.w = fmaf(w0, a1.y, acc0.w);
        acc1.x = fmaf(w1, c0.x, acc1.x);
        acc1.y = fmaf(w1, c0.y, acc1.y);
        acc1.z = fmaf(w1, c1.x, acc1.z);
        acc1.w = fmaf(w1, c1.y, acc1.w);
    }
    if (s < end) {
        const int2 e0 = edge[s];
        const float w = __int_as_float(e0.y);
        const uint2 hv = h2[e0.x * 16 + sub];
        const float2 a0 = __half22float2(*reinterpret_cast<const __half2*>(&hv.x));
        const float2 a1 = __half22float2(*reinterpret_cast<const __half2*>(&hv.y));
        acc0.x = fmaf(w, a0.x, acc0.x);
        acc0.y = fmaf(w, a0.y, acc0.y);
        acc0.z = fmaf(w, a1.x, acc0.z);
        acc0.w = fmaf(w, a1.y, acc0.w);
    }

    const float di = dinv[n];
    const uint2 hn = h2[n * 16 + sub];
    const float2 s0 = __half22float2(*reinterpret_cast<const __half2*>(&hn.x));
    const float2 s1 = __half22float2(*reinterpret_cast<const __half2*>(&hn.y));
    const float4 bv = reinterpret_cast<const float4*>(b)[sub];
    const float o0 = fmaf(di, acc0.x + acc1.x + s0.x, bv.x);
    const float o1 = fmaf(di, acc0.y + acc1.y + s0.y, bv.y);
    const float o2 = fmaf(di, acc0.z + acc1.z + s1.x, bv.z);
    const float o3 = fmaf(di, acc0.w + acc1.w + s1.y, bv.w);

    __half2 p0 = __floats2half2_rn(o0, o1);
    __half2 p1 = __floats2half2_rn(o2, o3);
    uint2 outv;
    outv.x = *reinterpret_cast<unsigned int*>(&p0);
    outv.y = *reinterpret_cast<unsigned int*>(&p1);
    agg2[n * 16 + sub] = outv;
}

// ---------------- fused MLP head: wmma stage1 + SIMT stage2 + sigmoid ----------------
__global__ void mlp_kernel(const __half* __restrict__ A,
                           const float* __restrict__ Wm1,
                           const float* __restrict__ bm1,
                           const float* __restrict__ Wm2,
                           const float* __restrict__ bm2,
                           float* __restrict__ out) {
    __shared__ __half Xh[64][72];
    __shared__ __half W1h[64][72];
    __shared__ float  T[64][68];
    __shared__ float  W2s[64][NCLS];
    __shared__ float  b1s[64];
    __shared__ float  b2s[NCLS];

    const int tid = threadIdx.x;
    const int warp = tid >> 5;
    const int rb = blockIdx.x * 64;
    const int rows = min(64, N_NODES - rb);

    for (int i = tid; i < 64 * 64; i += 256)
        W1h[i >> 6][i & 63] = __float2half(Wm1[i]);
    for (int i = tid; i < 64 * NCLS; i += 256)
        W2s[i / NCLS][i % NCLS] = Wm2[i];
    if (tid < 64) b1s[tid] = bm1[tid];
    if (tid < NCLS) b2s[tid] = bm2[tid];
    for (int i = tid; i < rows * 64; i += 256)
        Xh[i >> 6][i & 63] = __float2half(fmaxf(__half2float(A[rb * 64 + i]), 0.0f));
    if (rows < 64) {
        for (int i = rows * 64 + tid; i < 64 * 64; i += 256)
            Xh[i >> 6][i & 63] = __half(0.0f);
    }
    __syncthreads();

    // stage 1: T = relu(relu(A) @ Wm1 + bm1) via wmma (16 tiles, 2 per warp)
    {
        wmma::fragment<wmma::matrix_a, 16, 16, 16, __half, wmma::row_major> a;
        wmma::fragment<wmma::matrix_b, 16, 16, 16, __half, wmma::row_major> bf;
        wmma::fragment<wmma::accumulator, 16, 16, 16, float> c;
        #pragma unroll
        for (int i = 0; i < 2; i++) {
            const int t  = warp * 2 + i;
            const int tr = t >> 2;
            const int tc = t & 3;
            wmma::fill_fragment(c, 0.0f);
            #pragma unroll
            for (int kk = 0; kk < 4; kk++) {
                wmma::load_matrix_sync(a, &Xh[tr * 16][kk * 16], 72);
                wmma::load_matrix_sync(bf, &W1h[kk * 16][tc * 16], 72);
                wmma::mma_sync(c, a, bf, c);
            }
            wmma::store_matrix_sync(&T[tr * 16][tc * 16], c, 68, wmma::mem_row_major);
        }
    }
    __syncthreads();

    // bias + relu sweep
    for (int i = tid; i < 64 * 64; i += 256) {
        const int r = i >> 6, cc = i & 63;
        T[r][cc] = fmaxf(T[r][cc] + b1s[cc], 0.0f);
    }
    __syncthreads();

    // stage 2: out = sigmoid(T @ Wm2 + bm2); 256 threads = 16 rows x 16 cls
    const int row16 = tid >> 4;
    const int cls   = tid & 15;
    #pragma unroll
    for (int rr = 0; rr < 4; rr++) {
        const int row = rr * 16 + row16;
        const int gr = rb + row;
        float acc2 = b2s[cls];
        #pragma unroll
        for (int k = 0; k < 64; k++)
            acc2 = fmaf(T[row][k], W2s[k][cls], acc2);
        if (gr < N_NODES)
            out[gr * NCLS + cls] = 1.0f / (1.0f + __expf(-acc2));
    }
}

// ---------------- launch ----------------
extern "C" void kernel_launch(void* const* d_in, const int* in_sizes, int n_in,
                              void* d_out, int out_size) {
    const float* x    = (const float*)d_in[0];
    const int*   ei   = (const int*)d_in[1];
    const float* ew   = (const float*)d_in[2];
    const float* W1   = (const float*)d_in[3];
    const float* b1   = (const float*)d_in[4];
    const float* W2   = (const float*)d_in[5];
    const float* b2   = (const float*)d_in[6];
    const float* Wm1  = (const float*)d_in[7];
    const float* bm1  = (const float*)d_in[8];
    const float* Wm2  = (const float*)d_in[9];
    const float* bm2  = (const float*)d_in[10];
    float* out = (float*)d_out;

    float2 *p_dc;
    float *p_dinv;
    int *p_count, *p_off, *p_cursor, *p_total;
    int2 *p_edge;
    uint2 *p_h2, *p_agg2;
    cudaGetSymbolAddress((void**)&p_dc,     g_dc);
    cudaGetSymbolAddress((void**)&p_dinv,   g_dinv);
    cudaGetSymbolAddress((void**)&p_count,  g_count);
    cudaGetSymbolAddress((void**)&p_off,    g_off);
    cudaGetSymbolAddress((void**)&p_cursor, g_cursor);
    cudaGetSymbolAddress((void**)&p_total,  g_total);
    cudaGetSymbolAddress((void**)&p_edge,   g_edge);
    cudaGetSymbolAddress((void**)&p_h2,     g_h2);
    cudaGetSymbolAddress((void**)&p_agg2,   g_agg2);
    __half* p_h   = (__half*)p_h2;
    __half* p_agg = (__half*)p_agg2;

    const dim3 blkg(16, GATHER_NODES_PER_BLOCK);
    const int GATHER_GRID = (N_NODES + GATHER_NODES_PER_BLOCK - 1) / GATHER_NODES_PER_BLOCK;

    // CSR build (reused by both layers; dc/total invariants restored in-pipeline)
    deg_count_kernel<<<(N_EDGES + 255) / 256, 256>>>(ei, ew, p_dc);
    alloc_kernel<<<(N_NODES + 255) / 256, 256>>>(p_dc, p_count, p_dinv, p_off, p_cursor, p_total);
    fill_kernel<<<(N_EDGES + 255) / 256, 256>>>(ei, ew, p_cursor, p_edge);

    // layer 1
    gemm64_wmma_kernel<false><<<ROW_TILES, 256>>>(x, W1, p_dinv, p_h);
    gather_kernel<true><<<GATHER_GRID, blkg>>>(p_off, p_count, p_edge, p_dinv, b1, p_h2, p_agg2, p_total);

    // layer 2
    gemm64_wmma_kernel<true><<<ROW_TILES, 256>>>(p_agg, W2, p_dinv, p_h);
    gather_kernel<false><<<GATHER_GRID, blkg>>>(p_off, p_count, p_edge, p_dinv, b2, p_h2, p_agg2, p_total);

    // MLP head + sigmoid
    mlp_kernel<<<ROW_TILES, 256>>>(p_agg, Wm1, bm1, Wm2, bm2, out);
}

// round 17
// speedup vs baseline: 1.0846x; 1.0670x over previous
#include <cuda_runtime.h>
#include <cuda_fp16.h>
#include <mma.h>

using namespace nvcuda;

#define N_NODES 50000
#define N_EDGES 800000
#define D 64
#define NCLS 16
#define ROW_TILES ((N_NODES + 63) / 64)     // 782
#define GATHER_NODES_PER_BLOCK 16

// ---------------- scratch (zero-initialized at module load) ----------------
__device__ float2 g_dc[N_NODES];      // .x = sum of edge w into node, .y = count (restored to 0 by alloc)
__device__ float  g_dinv[N_NODES];
__device__ int    g_count[N_NODES];
__device__ int    g_off[N_NODES];
__device__ int    g_cursor[N_NODES];
__device__ int    g_total;            // restored to 0 by gather<true>
__device__ int2   g_edge[N_EDGES];    // CSR slot: {src, w bits}
__device__ __half g_wh[3 * 4096];     // fp16 weights: [W1 | W2 | Wm1]
__device__ uint2  g_h2[N_NODES * 16]; // h' = dinv*h in fp16
__device__ uint2  g_agg2[N_NODES * 16]; // agg in fp16

// ---------------- weights fp32 -> fp16 (once per launch) ----------------
__global__ void wconv_kernel(const float* __restrict__ W1,
                             const float* __restrict__ W2,
                             const float* __restrict__ Wm1,
                             __half* __restrict__ wh) {
    int i = blockIdx.x * blockDim.x + threadIdx.x;
    if (i < 4096)        wh[i] = __float2half(W1[i]);
    else if (i < 8192)   wh[i] = __float2half(W2[i - 4096]);
    else if (i < 12288)  wh[i] = __float2half(Wm1[i - 8192]);
}

// ---------------- weighted degree + count: one v2 vector RED per edge ----------------
__global__ void deg_count_kernel(const int* __restrict__ ei,
                                 const float* __restrict__ ew,
                                 float2* dc) {
    int e = blockIdx.x * blockDim.x + threadIdx.x;
    if (e < N_EDGES) {
        int c = ei[N_EDGES + e];
        float w = ew[e];
        asm volatile("red.global.add.v2.f32 [%0], {%1, %2};"
                     :: "l"(dc + c), "f"(w), "f"(1.0f) : "memory");
    }
}

// ---------------- alloc: dinv + warp-aggregated slot allocation; restores dc=0 ----------------
__global__ void alloc_kernel(float2* __restrict__ dc,
                             int* __restrict__ count,
                             float* __restrict__ dinv,
                             int* __restrict__ off,
                             int* __restrict__ cursor,
                             int* __restrict__ total) {
    const int i = blockIdx.x * blockDim.x + threadIdx.x;
    const int lane = threadIdx.x & 31;

    int c = 0;
    if (i < N_NODES) {
        float2 v = dc[i];
        dc[i] = make_float2(0.0f, 0.0f);   // restore invariant for next launch
        c = (int)v.y;
        dinv[i] = rsqrtf(1.0f + v.x);      // self-loop weight 1 added here
        count[i] = c;
    }

    int incl = c;
    #pragma unroll
    for (int d = 1; d < 32; d <<= 1) {
        int v = __shfl_up_sync(0xFFFFFFFFu, incl, d);
        if (lane >= d) incl += v;
    }
    const int warpsum = __shfl_sync(0xFFFFFFFFu, incl, 31);

    int base = 0;
    if (lane == 31) base = atomicAdd(total, warpsum);
    base = __shfl_sync(0xFFFFFFFFu, base, 31);

    const int o = base + incl - c;
    if (i < N_NODES) { off[i] = o; cursor[i] = o; }
}

// ---------------- CSR fill: one packed 8B (src, w) store per slot ----------------
__global__ void fill_kernel(const int* __restrict__ ei,
                            const float* __restrict__ ew,
                            int* __restrict__ cursor,
                            int2* __restrict__ edge) {
    int e = blockIdx.x * blockDim.x + threadIdx.x;
    if (e < N_EDGES) {
        int r = ei[e];
        int c = ei[N_EDGES + e];
        float w = ew[e];
        int slot = atomicAdd(&cursor[c], 1);
        edge[slot] = make_int2(r, __float_as_int(w));
    }
}

// ---------------- tensor-core 64x64 GEMM: h'fp16 = dinv * ((relu?)(X) @ W) ----------------
// W staged from pre-converted fp16 via vectorized copies; fp16 inputs staged
// with uint2 copies + hmax2 relu (no converts). Only fp32 input converts.
template <bool RELU_IN, typename TIN>
__global__ void gemm64_wmma_kernel(const TIN* __restrict__ X,
                                   const __half* __restrict__ Wg,
                                   const float* __restrict__ dinv,
                                   __half* __restrict__ H) {
    __shared__ __half Xh[64][72];               // 144B row pitch
    __shared__ __half Wh[64][72];
    __shared__ float  scratch[8][16][20];

    const int tid = threadIdx.x;
    const int warp = tid >> 5;
    const int lane = tid & 31;
    const int rb = blockIdx.x * 64;
    const int rows = min(64, N_NODES - rb);

    // stage W: 1024 uint2 (4 halves each), vectorized, no converts
    for (int j = tid; j < 1024; j += 256) {
        const int row = j >> 4, c4 = (j & 15) << 2;
        *reinterpret_cast<uint2*>(&Wh[row][c4]) = reinterpret_cast<const uint2*>(Wg)[j];
    }
    // stage X
    if constexpr (sizeof(TIN) == 2) {           // fp16 input: uint2 copy + hmax2 relu
        const uint2* Xg = reinterpret_cast<const uint2*>(X) + rb * 16;
        const __half2 zero2 = __half2half2(__float2half(0.0f));
        for (int j = tid; j < rows * 16; j += 256) {
            const int row = j >> 4, c4 = (j & 15) << 2;
            uint2 v = Xg[j];
            if (RELU_IN) {
                __half2 h0 = __hmax2(*reinterpret_cast<__half2*>(&v.x), zero2);
                __half2 h1 = __hmax2(*reinterpret_cast<__half2*>(&v.y), zero2);
                v.x = *reinterpret_cast<unsigned int*>(&h0);
                v.y = *reinterpret_cast<unsigned int*>(&h1);
            }
            *reinterpret_cast<uint2*>(&Xh[row][c4]) = v;
        }
    } else {                                    // fp32 input: scalar convert
        for (int i = tid; i < rows * 64; i += 256) {
            float v = X[rb * 64 + i];
            if (RELU_IN) v = fmaxf(v, 0.0f);
            Xh[i >> 6][i & 63] = __float2half(v);
        }
    }
    if (rows < 64) {
        for (int i = rows * 64 + tid; i < 64 * 64; i += 256)
            Xh[i >> 6][i & 63] = __half(0.0f);
    }
    __syncthreads();

    wmma::fragment<wmma::matrix_a, 16, 16, 16, __half, wmma::row_major> a;
    wmma::fragment<wmma::matrix_b, 16, 16, 16, __half, wmma::row_major> bf;
    wmma::fragment<wmma::accumulator, 16, 16, 16, float> c;

    #pragma unroll
    for (int i = 0; i < 2; i++) {
        const int t  = warp * 2 + i;
        const int tr = t >> 2;
        const int tc = t & 3;
        wmma::fill_fragment(c, 0.0f);
        #pragma unroll
        for (int kk = 0; kk < 4; kk++) {
            wmma::load_matrix_sync(a, &Xh[tr * 16][kk * 16], 72);
            wmma::load_matrix_sync(bf, &Wh[kk * 16][tc * 16], 72);
            wmma::mma_sync(c, a, bf, c);
        }
        wmma::store_matrix_sync(&scratch[warp][0][0], c, 20, wmma::mem_row_major);
        __syncwarp();
        #pragma unroll
        for (int j = lane; j < 128; j += 32) {
            const int r  = j >> 3;
            const int cc = (j & 7) * 2;
            const int gr = rb + tr * 16 + r;
            if (gr < N_NODES) {
                const float dv = dinv[gr];
                __half2 hv = __floats2half2_rn(dv * scratch[warp][r][cc],
                                               dv * scratch[warp][r][cc + 1]);
                *reinterpret_cast<__half2*>(&H[gr * 64 + tc * 16 + cc]) = hv;
            }
        }
        __syncwarp();
    }
}

// ---------------- CSR gather: agg[n] = fp16( dinv[n]*(sum w*h'[src] + h'[n]) + b ) ----------------
template <bool ZERO_TOTAL>
__global__ void gather_kernel(const int* __restrict__ off,
                              const int* __restrict__ count,
                              const int2* __restrict__ edge,
                              const float* __restrict__ dinv,
                              const float* __restrict__ b,
                              const uint2* __restrict__ h2,
                              uint2* __restrict__ agg2,
                              int* __restrict__ total) {
    if (ZERO_TOTAL && blockIdx.x == 0 && threadIdx.x == 0 && threadIdx.y == 0)
        *total = 0;

    const int sub = threadIdx.x;
    const int n = blockIdx.x * GATHER_NODES_PER_BLOCK + threadIdx.y;
    if (n >= N_NODES) return;

    const int beg = off[n];
    const int end = beg + count[n];

    float4 acc0 = make_float4(0.f, 0.f, 0.f, 0.f);
    float4 acc1 = make_float4(0.f, 0.f, 0.f, 0.f);
    int s = beg;
    for (; s + 1 < end; s += 2) {
        const int2 e0 = edge[s];
        const int2 e1 = edge[s + 1];
        const float w0 = __int_as_float(e0.y);
        const float w1 = __int_as_float(e1.y);
        const uint2 hv0 = h2[e0.x * 16 + sub];
        const uint2 hv1 = h2[e1.x * 16 + sub];
        const float2 a0 = __half22float2(*reinterpret_cast<const __half2*>(&hv0.x));
        const float2 a1 = __half22float2(*reinterpret_cast<const __half2*>(&hv0.y));
        const float2 c0 = __half22float2(*reinterpret_cast<const __half2*>(&hv1.x));
        const float2 c1 = __half22float2(*reinterpret_cast<const __half2*>(&hv1.y));
        acc0.x = fmaf(w0, a0.x, acc0.x);
        acc0.y = fmaf(w0, a0.y, acc0.y);
        acc0.z = fmaf(w0, a1.x, acc0.z);
        acc0.w = fmaf(w0, a1.y, acc0.w);
        acc1.x = fmaf(w1, c0.x, acc1.x);
        acc1.y = fmaf(w1, c0.y, acc1.y);
        acc1.z = fmaf(w1, c1.x, acc1.z);
        acc1.w = fmaf(w1, c1.y, acc1.w);
    }
    if (s < end) {
        const int2 e0 = edge[s];
        const float w = __int_as_float(e0.y);
        const uint2 hv = h2[e0.x * 16 + sub];
        const float2 a0 = __half22float2(*reinterpret_cast<const __half2*>(&hv.x));
        const float2 a1 = __half22float2(*reinterpret_cast<const __half2*>(&hv.y));
        acc0.x = fmaf(w, a0.x, acc0.x);
        acc0.y = fmaf(w, a0.y, acc0.y);
        acc0.z = fmaf(w, a1.x, acc0.z);
        acc0.w = fmaf(w, a1.y, acc0.w);
    }

    const float di = dinv[n];
    const uint2 hn = h2[n * 16 + sub];
    const float2 s0 = __half22float2(*reinterpret_cast<const __half2*>(&hn.x));
    const float2 s1 = __half22float2(*reinterpret_cast<const __half2*>(&hn.y));
    const float4 bv = reinterpret_cast<const float4*>(b)[sub];
    const float o0 = fmaf(di, acc0.x + acc1.x + s0.x, bv.x);
    const float o1 = fmaf(di, acc0.y + acc1.y + s0.y, bv.y);
    const float o2 = fmaf(di, acc0.z + acc1.z + s1.x, bv.z);
    const float o3 = fmaf(di, acc0.w + acc1.w + s1.y, bv.w);

    __half2 p0 = __floats2half2_rn(o0, o1);
    __half2 p1 = __floats2half2_rn(o2, o3);
    uint2 outv;
    outv.x = *reinterpret_cast<unsigned int*>(&p0);
    outv.y = *reinterpret_cast<unsigned int*>(&p1);
    agg2[n * 16 + sub] = outv;
}

// ---------------- fused MLP head: wmma stage1 + SIMT stage2 + sigmoid ----------------
__global__ void mlp_kernel(const __half* __restrict__ A,
                           const __half* __restrict__ W1g,   // pre-converted fp16 Wm1
                           const float* __restrict__ bm1,
                           const float* __restrict__ Wm2,
                           const float* __restrict__ bm2,
                           float* __restrict__ out) {
    __shared__ __half Xh[64][72];
    __shared__ __half W1h[64][72];
    __shared__ float  T[64][68];
    __shared__ float  W2s[64][NCLS];
    __shared__ float  b1s[64];
    __shared__ float  b2s[NCLS];

    const int tid = threadIdx.x;
    const int warp = tid >> 5;
    const int rb = blockIdx.x * 64;
    const int rows = min(64, N_NODES - rb);

    // stage Wm1: vectorized fp16 copy, no converts
    for (int j = tid; j < 1024; j += 256) {
        const int row = j >> 4, c4 = (j & 15) << 2;
        *reinterpret_cast<uint2*>(&W1h[row][c4]) = reinterpret_cast<const uint2*>(W1g)[j];
    }
    for (int i = tid; i < 64 * NCLS; i += 256)
        W2s[i / NCLS][i % NCLS] = Wm2[i];
    if (tid < 64) b1s[tid] = bm1[tid];
    if (tid < NCLS) b2s[tid] = bm2[tid];
    // stage A (fp16) with hmax2 relu, no converts
    {
        const uint2* Xg = reinterpret_cast<const uint2*>(A) + rb * 16;
        const __half2 zero2 = __half2half2(__float2half(0.0f));
        for (int j = tid; j < rows * 16; j += 256) {
            const int row = j >> 4, c4 = (j & 15) << 2;
            uint2 v = Xg[j];
            __half2 h0 = __hmax2(*reinterpret_cast<__half2*>(&v.x), zero2);
            __half2 h1 = __hmax2(*reinterpret_cast<__half2*>(&v.y), zero2);
            v.x = *reinterpret_cast<unsigned int*>(&h0);
            v.y = *reinterpret_cast<unsigned int*>(&h1);
            *reinterpret_cast<uint2*>(&Xh[row][c4]) = v;
        }
    }
    if (rows < 64) {
        for (int i = rows * 64 + tid; i < 64 * 64; i += 256)
            Xh[i >> 6][i & 63] = __half(0.0f);
    }
    __syncthreads();

    // stage 1: T = relu(relu(A) @ Wm1 + bm1) via wmma
    {
        wmma::fragment<wmma::matrix_a, 16, 16, 16, __half, wmma::row_major> a;
        wmma::fragment<wmma::matrix_b, 16, 16, 16, __half, wmma::row_major> bf;
        wmma::fragment<wmma::accumulator, 16, 16, 16, float> c;
        #pragma unroll
        for (int i = 0; i < 2; i++) {
            const int t  = warp * 2 + i;
            const int tr = t >> 2;
            const int tc = t & 3;
            wmma::fill_fragment(c, 0.0f);
            #pragma unroll
            for (int kk = 0; kk < 4; kk++) {
                wmma::load_matrix_sync(a, &Xh[tr * 16][kk * 16], 72);
                wmma::load_matrix_sync(bf, &W1h[kk * 16][tc * 16], 72);
                wmma::mma_sync(c, a, bf, c);
            }
            wmma::store_matrix_sync(&T[tr * 16][tc * 16], c, 68, wmma::mem_row_major);
        }
    }
    __syncthreads();

    for (int i = tid; i < 64 * 64; i += 256) {
        const int r = i >> 6, cc = i & 63;
        T[r][cc] = fmaxf(T[r][cc] + b1s[cc], 0.0f);
    }
    __syncthreads();

    const int row16 = tid >> 4;
    const int cls   = tid & 15;
    #pragma unroll
    for (int rr = 0; rr < 4; rr++) {
        const int row = rr * 16 + row16;
        const int gr = rb + row;
        float acc2 = b2s[cls];
        #pragma unroll
        for (int k = 0; k < 64; k++)
            acc2 = fmaf(T[row][k], W2s[k][cls], acc2);
        if (gr < N_NODES)
            out[gr * NCLS + cls] = 1.0f / (1.0f + __expf(-acc2));
    }
}

// ---------------- launch ----------------
extern "C" void kernel_launch(void* const* d_in, const int* in_sizes, int n_in,
                              void* d_out, int out_size) {
    const float* x    = (const float*)d_in[0];
    const int*   ei   = (const int*)d_in[1];
    const float* ew   = (const float*)d_in[2];
    const float* W1   = (const float*)d_in[3];
    const float* b1   = (const float*)d_in[4];
    const float* W2   = (const float*)d_in[5];
    const float* b2   = (const float*)d_in[6];
    const float* Wm1  = (const float*)d_in[7];
    const float* bm1  = (const float*)d_in[8];
    const float* Wm2  = (const float*)d_in[9];
    const float* bm2  = (const float*)d_in[10];
    float* out = (float*)d_out;

    float2 *p_dc;
    float *p_dinv;
    int *p_count, *p_off, *p_cursor, *p_total;
    int2 *p_edge;
    __half *p_wh;
    uint2 *p_h2, *p_agg2;
    cudaGetSymbolAddress((void**)&p_dc,     g_dc);
    cudaGetSymbolAddress((void**)&p_dinv,   g_dinv);
    cudaGetSymbolAddress((void**)&p_count,  g_count);
    cudaGetSymbolAddress((void**)&p_off,    g_off);
    cudaGetSymbolAddress((void**)&p_cursor, g_cursor);
    cudaGetSymbolAddress((void**)&p_total,  g_total);
    cudaGetSymbolAddress((void**)&p_edge,   g_edge);
    cudaGetSymbolAddress((void**)&p_wh,     g_wh);
    cudaGetSymbolAddress((void**)&p_h2,     g_h2);
    cudaGetSymbolAddress((void**)&p_agg2,   g_agg2);
    __half* p_h   = (__half*)p_h2;
    __half* p_agg = (__half*)p_agg2;

    const dim3 blkg(16, GATHER_NODES_PER_BLOCK);
    const int GATHER_GRID = (N_NODES + GATHER_NODES_PER_BLOCK - 1) / GATHER_NODES_PER_BLOCK;

    // weights -> fp16 (once)
    wconv_kernel<<<48, 256>>>(W1, W2, Wm1, p_wh);

    // CSR build (reused by both layers; dc/total invariants restored in-pipeline)
    deg_count_kernel<<<(N_EDGES + 255) / 256, 256>>>(ei, ew, p_dc);
    alloc_kernel<<<(N_NODES + 255) / 256, 256>>>(p_dc, p_count, p_dinv, p_off, p_cursor, p_total);
    fill_kernel<<<(N_EDGES + 255) / 256, 256>>>(ei, ew, p_cursor, p_edge);

    // layer 1
    gemm64_wmma_kernel<false><<<ROW_TILES, 256>>>(x, p_wh, p_dinv, p_h);
    gather_kernel<true><<<GATHER_GRID, blkg>>>(p_off, p_count, p_edge, p_dinv, b1, p_h2, p_agg2, p_total);

    // layer 2
    gemm64_wmma_kernel<true><<<ROW_TILES, 256>>>(p_agg, p_wh + 4096, p_dinv, p_h);
    gather_kernel<false><<<GATHER_GRID, blkg>>>(p_off, p_count, p_edge, p_dinv, b2, p_h2, p_agg2, p_total);

    // MLP head + sigmoid
    mlp_kernel<<<ROW_TILES, 256>>>(p_agg, p_wh + 8192, bm1, Wm2, bm2, out);
}